// round 2
// baseline (speedup 1.0000x reference)
#include <cuda_runtime.h>
#include <math.h>

typedef unsigned long long u64;
typedef unsigned int u32;

#define HH 128
#define WW 192
#define NA 9
#define NTOT (HH*WW*NA)      /* 221184 */
#define HW   (HH*WW)
#define PRE_K 6000
#define POST_K 300
#define NW 94                /* ceil(6000/64) */
#define NBINS 65536
#define SORT_CAP 8192

/* ---------------- scratch (no allocation allowed) ---------------- */
__device__ float4 g_boxes[NTOT];
__device__ u32    g_key[NTOT];
__device__ u32    g_hist[NBINS];
__device__ u32    g_threshbin;
__device__ u32    g_candcount;
__device__ u64    g_cand[SORT_CAP];
__device__ float4 g_nboxes[PRE_K];
__device__ u64    g_tvalid[NW];
__device__ u64    g_mask[(size_t)PRE_K * NW];   /* 4.5 MB */
__device__ u64    g_keep[NW];

/* anchors from _generate_anchors(16,(.5,1,2),(8,16,32)) */
__constant__ float c_anch[NA][4] = {
    {-84.f,  -40.f,  99.f,  55.f},
    {-176.f, -88.f,  191.f, 103.f},
    {-360.f, -184.f, 375.f, 199.f},
    {-56.f,  -56.f,  71.f,  71.f},
    {-120.f, -120.f, 135.f, 135.f},
    {-248.f, -248.f, 263.f, 263.f},
    {-36.f,  -80.f,  51.f,  95.f},
    {-80.f,  -168.f, 95.f,  183.f},
    {-168.f, -344.f, 183.f, 359.f}
};

/* ---------------- K0: zero scratch ---------------- */
__global__ void zero_kernel() {
    int i = blockIdx.x * 256 + threadIdx.x;
    if (i < NBINS) { g_hist[i] = 0u; return; }
    int j = i - NBINS;
    if (j < NW) { g_tvalid[j] = 0ull; return; }
    j -= NW;
    if (j < NW) { g_keep[j] = 0ull; return; }
    j -= NW;
    if (j == 0) g_candcount = 0u;
    else if (j == 1) g_threshbin = NBINS - 1;
}

/* ---------------- K1: decode + score key + histogram ---------------- */
__global__ void decode_kernel(const float* __restrict__ scores,
                              const float* __restrict__ deltas,
                              const float* __restrict__ iminfo) {
    int i = blockIdx.x * 256 + threadIdx.x;       /* grid covers NTOT exactly */
    int y = i / (WW * NA);
    int r = i - y * (WW * NA);
    int x = r / NA;
    int a = r - x * NA;

    float sx = 16.f * (float)x;
    float sy = 16.f * (float)y;
    float ax1 = c_anch[a][0] + sx;
    float ay1 = c_anch[a][1] + sy;
    float aw  = (c_anch[a][2] - c_anch[a][0]) + 1.f;   /* exact */
    float ah  = (c_anch[a][3] - c_anch[a][1]) + 1.f;
    float cx  = __fadd_rn(ax1, 0.5f * aw);
    float cy  = __fadd_rn(ay1, 0.5f * ah);

    int sp = y * WW + x;
    float dx = deltas[(4*a+0)*HW + sp];
    float dy = deltas[(4*a+1)*HW + sp];
    float dw = fminf(fmaxf(deltas[(4*a+2)*HW + sp], -10.f), 10.f);
    float dh = fminf(fmaxf(deltas[(4*a+3)*HW + sp], -10.f), 10.f);

    float pcx = __fadd_rn(__fmul_rn(dx, aw), cx);
    float pcy = __fadd_rn(__fmul_rn(dy, ah), cy);
    float pw  = __fmul_rn(expf(dw), aw);
    float ph  = __fmul_rn(expf(dh), ah);
    float hx  = __fmul_rn(0.5f, pw);
    float hy  = __fmul_rn(0.5f, ph);
    float x1 = __fsub_rn(pcx, hx), x2 = __fadd_rn(pcx, hx);
    float y1 = __fsub_rn(pcy, hy), y2 = __fadd_rn(pcy, hy);

    float xmax = __fsub_rn(iminfo[1], 1.f);
    float ymax = __fsub_rn(iminfo[0], 1.f);
    x1 = fminf(fmaxf(x1, 0.f), xmax);
    x2 = fminf(fmaxf(x2, 0.f), xmax);
    y1 = fminf(fmaxf(y1, 0.f), ymax);
    y2 = fminf(fmaxf(y2, 0.f), ymax);

    float minsz = __fmul_rn(16.f, iminfo[2]);
    bool valid = (__fadd_rn(__fsub_rn(x2, x1), 1.f) >= minsz) &&
                 (__fadd_rn(__fsub_rn(y2, y1), 1.f) >= minsz);

    float sc = scores[(NA + a)*HW + sp];
    u32 u = valid ? __float_as_uint(sc) : 0xFF800000u;   /* -inf if invalid */
    u32 m = (u & 0x80000000u) ? ~u : (u | 0x80000000u);  /* ascending map */
    u32 key = ~m;                                        /* descending: big score -> small key */

    g_boxes[i] = make_float4(x1, y1, x2, y2);
    g_key[i]   = key;
    atomicAdd(&g_hist[key >> 16], 1u);
}

/* ---------------- K2: find threshold bin (first bin with cum >= PRE_K) ---- */
__global__ void thresh_kernel() {
    __shared__ u32 ss[1024];
    int t = threadIdx.x;
    int base = t * 64;
    u32 v = 0;
    #pragma unroll 8
    for (int b = 0; b < 64; b++) v += g_hist[base + b];
    ss[t] = v;
    __syncthreads();
    for (int off = 1; off < 1024; off <<= 1) {
        u32 x = (t >= off) ? ss[t - off] : 0u;
        __syncthreads();
        ss[t] += x;
        __syncthreads();
    }
    u32 incl = ss[t], excl = incl - v;
    if (excl < PRE_K && incl >= PRE_K) {
        u32 cum = excl;
        for (int b = 0; b < 64; b++) {
            cum += g_hist[base + b];
            if (cum >= PRE_K) { g_threshbin = (u32)(base + b); break; }
        }
    }
}

/* ---------------- K3: compact candidates ---------------- */
__global__ void compact_kernel() {
    int i = blockIdx.x * 256 + threadIdx.x;
    u32 key = g_key[i];
    if ((key >> 16) <= g_threshbin) {
        u32 pos = atomicAdd(&g_candcount, 1u);
        if (pos < SORT_CAP) g_cand[pos] = ((u64)key << 32) | (u32)i;
    }
}

/* ---------------- K4: single-block bitonic sort of 8192 keys ------------- */
__global__ void sort_kernel() {
    extern __shared__ u64 s[];
    int t = threadIdx.x;
    u32 cnt = g_candcount; if (cnt > SORT_CAP) cnt = SORT_CAP;
    for (int i = t; i < SORT_CAP; i += 1024) s[i] = (i < (int)cnt) ? g_cand[i] : ~0ull;
    __syncthreads();
    for (int k = 2; k <= SORT_CAP; k <<= 1) {
        for (int j = k >> 1; j > 0; j >>= 1) {
            for (int i = t; i < SORT_CAP; i += 1024) {
                int ixj = i ^ j;
                if (ixj > i) {
                    u64 a = s[i], b = s[ixj];
                    bool up = ((i & k) == 0);
                    if ((a > b) == up) { s[i] = b; s[ixj] = a; }
                }
            }
            __syncthreads();
        }
    }
    for (int i = t; i < SORT_CAP; i += 1024) g_cand[i] = s[i];
}

/* ---------------- K5: gather top-6000 boxes + validity bits -------------- */
__global__ void gather_kernel() {
    int c = blockIdx.x;          /* NW blocks */
    int t = threadIdx.x;         /* 64 */
    int j = c * 64 + t;
    u64 key = g_cand[j];
    bool valid = (j < PRE_K) && ((u32)(key >> 32) < 0xFF800000u);
    if (j < PRE_K) {
        u32 idx = (u32)key;
        if (idx < NTOT) g_nboxes[j] = g_boxes[idx];
        else            g_nboxes[j] = make_float4(0.f, 0.f, 0.f, 0.f);
    }
    u32 b = __ballot_sync(0xffffffffu, valid);
    if ((t & 31) == 0) atomicOr(&g_tvalid[c], ((u64)b) << ((t >> 5) * 32));
}

/* ---------------- K6: 6000x6000 IoU bitmask ---------------- */
__global__ void iou_kernel() {
    __shared__ float4 sb[64];
    __shared__ float  sa[64];
    int cb = blockIdx.x, rb = blockIdx.y, t = threadIdx.x;
    int j = cb * 64 + t;
    float4 bj = (j < PRE_K) ? g_nboxes[j] : make_float4(0.f, 0.f, 0.f, 0.f);
    sb[t] = bj;
    sa[t] = __fmul_rn(__fsub_rn(bj.z, bj.x), __fsub_rn(bj.w, bj.y));
    __syncthreads();
    int i = rb * 64 + t;
    if (i >= PRE_K) return;
    float4 bi = g_nboxes[i];
    float ai = __fmul_rn(__fsub_rn(bi.z, bi.x), __fsub_rn(bi.w, bi.y));
    u64 bits = 0ull;
    int cmax = PRE_K - cb * 64; if (cmax > 64) cmax = 64;
    for (int c = 0; c < cmax; ++c) {
        float4 bc = sb[c];
        float lx = fmaxf(bi.x, bc.x), ly = fmaxf(bi.y, bc.y);
        float rx = fminf(bi.z, bc.z), ry = fminf(bi.w, bc.w);
        float w = fmaxf(__fsub_rn(rx, lx), 0.f);
        float h = fmaxf(__fsub_rn(ry, ly), 0.f);
        float inter = __fmul_rn(w, h);
        float denom = __fsub_rn(__fadd_rn(ai, sa[c]), inter);
        float iou = inter / denom;              /* NaN > 0.7f == false, matches JAX */
        if (iou > 0.7f) bits |= (1ull << c);
    }
    g_mask[(size_t)i * NW + cb] = bits;
}

/* ---------------- K7: single-warp greedy NMS scan (early exit @300) ------ */
__global__ void nms_scan_kernel() {
    const unsigned FULL = 0xffffffffu;
    int lane = threadIdx.x;
    int w0 = 3 * lane;
    u64 rm0 = 0, rm1 = 0, rm2 = 0;
    u64 tv0 = (w0 + 0 < NW) ? g_tvalid[w0 + 0] : 0ull;
    u64 tv1 = (w0 + 1 < NW) ? g_tvalid[w0 + 1] : 0ull;
    u64 tv2 = (w0 + 2 < NW) ? g_tvalid[w0 + 2] : 0ull;
    int kept_total = 0;

    for (int c = 0; c < NW; ++c) {
        int owner = c / 3;
        int slot  = c - 3 * owner;
        u64 myrem = (slot == 0) ? rm0 : ((slot == 1) ? rm1 : rm2);
        u64 mytv  = (slot == 0) ? tv0 : ((slot == 1) ? tv1 : tv2);
        u64 rem_c = __shfl_sync(FULL, myrem, owner);
        u64 tv_c  = __shfl_sync(FULL, mytv,  owner);

        int r0 = c * 64 + 2 * lane;
        int r1 = r0 + 1;
        u64 m0 = (r0 < PRE_K) ? g_mask[(size_t)r0 * NW + c] : 0ull;
        u64 m1 = (r1 < PRE_K) ? g_mask[(size_t)r1 * NW + c] : 0ull;

        u64 local = rem_c, keptmask = 0ull;
        #pragma unroll
        for (int k = 0; k < 64; ++k) {
            u64 v = __shfl_sync(FULL, (k & 1) ? m1 : m0, k >> 1);
            bool kp = (((tv_c >> k) & 1ull) != 0ull) && (((local >> k) & 1ull) == 0ull);
            if (kp) { local |= v; keptmask |= (1ull << k); }
        }

        if (lane == 0) g_keep[c] = keptmask;
        kept_total += __popcll(keptmask);
        if (kept_total >= POST_K) break;   /* later ranks never emitted */

        /* fold kept rows of this block into per-lane removed words */
        u64 mb = keptmask;
        while (mb) {
            int k = __ffsll((long long)mb) - 1;
            mb &= mb - 1;
            size_t base = (size_t)(c * 64 + k) * NW;
            if (w0 + 0 < NW) rm0 |= g_mask[base + w0 + 0];
            if (w0 + 1 < NW) rm1 |= g_mask[base + w0 + 1];
            if (w0 + 2 < NW) rm2 |= g_mask[base + w0 + 2];
        }
    }
}

/* ---------------- K8: emit first 300 kept rows ---------------- */
__global__ void output_kernel(float* __restrict__ out) {
    __shared__ u64 skeep[NW];
    __shared__ int spref[NW];
    int t = threadIdx.x;
    for (int i = t; i < POST_K * 5; i += 512) out[i] = 0.f;
    if (t < NW) skeep[t] = g_keep[t];
    __syncthreads();
    if (t == 0) {
        int run = 0;
        for (int w = 0; w < NW; ++w) { spref[w] = run; run += __popcll(skeep[w]); }
    }
    __syncthreads();
    for (int i = t; i < PRE_K; i += 512) {
        int w = i >> 6, b = i & 63;
        u64 kw = skeep[w];
        if ((kw >> b) & 1ull) {
            u64 lowmask = (b == 0) ? 0ull : ((~0ull) >> (64 - b));
            int rank = spref[w] + __popcll(kw & lowmask);
            if (rank < POST_K) {
                float4 bx = g_nboxes[i];
                out[rank * 5 + 1] = bx.x;
                out[rank * 5 + 2] = bx.y;
                out[rank * 5 + 3] = bx.z;
                out[rank * 5 + 4] = bx.w;
            }
        }
    }
}

/* ---------------- launch ---------------- */
extern "C" void kernel_launch(void* const* d_in, const int* in_sizes, int n_in,
                              void* d_out, int out_size) {
    const float* scores = (const float*)d_in[0];
    const float* deltas = (const float*)d_in[1];
    const float* iminfo = (const float*)d_in[2];
    float* out = (float*)d_out;

    cudaFuncSetAttribute(sort_kernel, cudaFuncAttributeMaxDynamicSharedMemorySize,
                         SORT_CAP * (int)sizeof(u64));

    zero_kernel<<<(NBINS + 2 * NW + 2 + 255) / 256, 256>>>();
    decode_kernel<<<NTOT / 256, 256>>>(scores, deltas, iminfo);
    thresh_kernel<<<1, 1024>>>();
    compact_kernel<<<NTOT / 256, 256>>>();
    sort_kernel<<<1, 1024, SORT_CAP * sizeof(u64)>>>();
    gather_kernel<<<NW, 64>>>();
    iou_kernel<<<dim3(NW, NW), 64>>>();
    nms_scan_kernel<<<1, 32>>>();
    output_kernel<<<1, 512>>>(out);
}

// round 3
// speedup vs baseline: 1.1996x; 1.1996x over previous
#include <cuda_runtime.h>
#include <math.h>

typedef unsigned long long u64;
typedef unsigned int u32;

#define HH 128
#define WW 192
#define NA 9
#define NTOT (HH*WW*NA)      /* 221184 */
#define HW   (HH*WW)
#define PRE_K 6000
#define POST_K 300
#define NW 94                /* ceil(6000/64) */
#define NWP 96               /* padded row stride (u64 words) */
#define NBINS 65536
#define SORT_CAP 8192

/* ---------------- scratch (no allocation allowed) ---------------- */
__device__ float4 g_boxes[NTOT];       /* (a, sp) layout */
__device__ u32    g_key[NTOT];         /* (a, sp) layout */
__device__ u32    g_hist[NBINS];
__device__ u32    g_threshbin;
__device__ u32    g_candcount;
__device__ u64    g_cand[SORT_CAP];
__device__ u64    g_srt[PRE_K];
__device__ float4 g_nboxes[PRE_K];
__device__ u64    g_tvalid[NWP];
__device__ u64    g_mask[(size_t)PRE_K * NWP];   /* 4.6 MB, padded words zero */
__device__ u64    g_keep[NWP];

/* anchors from _generate_anchors(16,(.5,1,2),(8,16,32)) */
__constant__ float c_anch[NA][4] = {
    {-84.f,  -40.f,  99.f,  55.f},
    {-176.f, -88.f,  191.f, 103.f},
    {-360.f, -184.f, 375.f, 199.f},
    {-56.f,  -56.f,  71.f,  71.f},
    {-120.f, -120.f, 135.f, 135.f},
    {-248.f, -248.f, 263.f, 263.f},
    {-36.f,  -80.f,  51.f,  95.f},
    {-80.f,  -168.f, 95.f,  183.f},
    {-168.f, -344.f, 183.f, 359.f}
};

/* ---------------- K0: zero/init scratch ---------------- */
__global__ void zero_kernel() {
    int i = blockIdx.x * 256 + threadIdx.x;
    if (i < NBINS) { g_hist[i] = 0u; return; }
    int j = i - NBINS;
    if (j < NWP) { g_tvalid[j] = 0ull; return; }
    j -= NWP;
    if (j < NWP) { g_keep[j] = 0ull; return; }
    j -= NWP;
    if (j < 2) { if (j == 0) g_candcount = 0u; else g_threshbin = NBINS - 1; return; }
    j -= 2;
    if (j < SORT_CAP) { g_cand[j] = ~0ull; return; }
    j -= SORT_CAP;
    if (j < PRE_K * 2) {      /* zero pad words 94,95 of every mask row */
        int r = j >> 1;
        g_mask[(size_t)r * NWP + NW + (j & 1)] = 0ull;
    }
}
#define ZERO_ITEMS (NBINS + 2*NWP + 2 + SORT_CAP + PRE_K*2)

/* ---------------- K1: decode + score key + histogram (coalesced) --------- */
__global__ void decode_kernel(const float* __restrict__ scores,
                              const float* __restrict__ deltas,
                              const float* __restrict__ iminfo) {
    int tid = blockIdx.x * 256 + threadIdx.x;     /* grid covers NTOT exactly */
    int a  = tid / HW;
    int sp = tid - a * HW;
    int y  = sp / WW;
    int x  = sp - y * WW;

    float sx = 16.f * (float)x;
    float sy = 16.f * (float)y;
    float ax1 = c_anch[a][0] + sx;
    float ay1 = c_anch[a][1] + sy;
    float aw  = (c_anch[a][2] - c_anch[a][0]) + 1.f;
    float ah  = (c_anch[a][3] - c_anch[a][1]) + 1.f;
    float cx  = __fadd_rn(ax1, 0.5f * aw);
    float cy  = __fadd_rn(ay1, 0.5f * ah);

    float dx = deltas[(4*a+0)*HW + sp];
    float dy = deltas[(4*a+1)*HW + sp];
    float dw = fminf(fmaxf(deltas[(4*a+2)*HW + sp], -10.f), 10.f);
    float dh = fminf(fmaxf(deltas[(4*a+3)*HW + sp], -10.f), 10.f);

    float pcx = __fadd_rn(__fmul_rn(dx, aw), cx);
    float pcy = __fadd_rn(__fmul_rn(dy, ah), cy);
    float pw  = __fmul_rn(expf(dw), aw);
    float ph  = __fmul_rn(expf(dh), ah);
    float hx  = __fmul_rn(0.5f, pw);
    float hy  = __fmul_rn(0.5f, ph);
    float x1 = __fsub_rn(pcx, hx), x2 = __fadd_rn(pcx, hx);
    float y1 = __fsub_rn(pcy, hy), y2 = __fadd_rn(pcy, hy);

    float xmax = __fsub_rn(iminfo[1], 1.f);
    float ymax = __fsub_rn(iminfo[0], 1.f);
    x1 = fminf(fmaxf(x1, 0.f), xmax);
    x2 = fminf(fmaxf(x2, 0.f), xmax);
    y1 = fminf(fmaxf(y1, 0.f), ymax);
    y2 = fminf(fmaxf(y2, 0.f), ymax);

    float minsz = __fmul_rn(16.f, iminfo[2]);
    bool valid = (__fadd_rn(__fsub_rn(x2, x1), 1.f) >= minsz) &&
                 (__fadd_rn(__fsub_rn(y2, y1), 1.f) >= minsz);

    float sc = scores[(NA + a)*HW + sp];
    u32 u = valid ? __float_as_uint(sc) : 0xFF800000u;
    u32 m = (u & 0x80000000u) ? ~u : (u | 0x80000000u);
    u32 key = ~m;                                  /* big score -> small key */

    g_boxes[tid] = make_float4(x1, y1, x2, y2);
    g_key[tid]   = key;
    atomicAdd(&g_hist[key >> 16], 1u);
}

/* ---------------- K2: find threshold bin ---------------- */
__global__ void thresh_kernel() {
    __shared__ u32 ss[1024];
    int t = threadIdx.x;
    int base = t * 64;
    u32 v = 0;
    #pragma unroll 8
    for (int b = 0; b < 64; b++) v += g_hist[base + b];
    ss[t] = v;
    __syncthreads();
    for (int off = 1; off < 1024; off <<= 1) {
        u32 x = (t >= off) ? ss[t - off] : 0u;
        __syncthreads();
        ss[t] += x;
        __syncthreads();
    }
    u32 incl = ss[t], excl = incl - v;
    if (excl < PRE_K && incl >= PRE_K) {
        u32 cum = excl;
        for (int b = 0; b < 64; b++) {
            cum += g_hist[base + b];
            if (cum >= PRE_K) { g_threshbin = (u32)(base + b); break; }
        }
    }
}

/* ---------------- K3: compact candidates (block-aggregated atomic) ------- */
__global__ void compact_kernel() {
    __shared__ u32 sbase;
    __shared__ u32 scnt;
    int tid = blockIdx.x * 256 + threadIdx.x;
    if (threadIdx.x == 0) scnt = 0u;
    __syncthreads();
    u32 key = g_key[tid];
    bool sel = (key >> 16) <= g_threshbin;
    u32 pos = 0;
    if (sel) pos = atomicAdd(&scnt, 1u);
    __syncthreads();
    if (threadIdx.x == 0) sbase = atomicAdd(&g_candcount, scnt);
    __syncthreads();
    if (sel) {
        int a = tid / HW, sp = tid - a * HW;
        u32 orig = (u32)(sp * NA + a);             /* reference ordering idx */
        u32 p = sbase + pos;
        if (p < SORT_CAP) g_cand[p] = ((u64)key << 32) | orig;
    }
}

/* ---------------- K4: rank-by-counting "sort" (replaces bitonic) --------- */
__global__ void rank_kernel() {
    __shared__ u64 tile[1024];
    int t = threadIdx.x;                           /* 128 */
    u64 mine = g_cand[blockIdx.x * 128 + t];
    int rank = 0;
    for (int base = 0; base < SORT_CAP; base += 1024) {
        __syncthreads();
        #pragma unroll
        for (int i = 0; i < 8; i++) tile[t + i * 128] = g_cand[base + t + i * 128];
        __syncthreads();
        #pragma unroll 16
        for (int i = 0; i < 1024; i++) rank += (tile[i] < mine) ? 1 : 0;
    }
    if (rank < PRE_K) g_srt[rank] = mine;
}

/* ---------------- K5: gather top-6000 boxes + validity bits -------------- */
__global__ void gather_kernel() {
    int c = blockIdx.x;          /* NW blocks */
    int t = threadIdx.x;         /* 64 */
    int j = c * 64 + t;
    bool valid = false;
    if (j < PRE_K) {
        u64 v = g_srt[j];
        u32 key = (u32)(v >> 32);
        valid = key < 0xFF800000u;
        u32 orig = (u32)v;
        int aa = orig % NA;
        int sp = orig / NA;
        g_nboxes[j] = g_boxes[aa * HW + sp];
    }
    u32 b = __ballot_sync(0xffffffffu, valid);
    if ((t & 31) == 0) atomicOr(&g_tvalid[c], ((u64)b) << ((t >> 5) * 32));
}

/* ---------------- K6: 6000x6000 IoU bitmask (2 rows / thread) ------------ */
__global__ void iou_kernel() {
    __shared__ float4 sb[64];
    __shared__ float  sa[64];
    int cb = blockIdx.x, rb = blockIdx.y, t = threadIdx.x;   /* 64 threads */
    int j = cb * 64 + t;
    float4 bj = (j < PRE_K) ? g_nboxes[j] : make_float4(0.f, 0.f, 0.f, 0.f);
    sb[t] = bj;
    sa[t] = __fmul_rn(__fsub_rn(bj.z, bj.x), __fsub_rn(bj.w, bj.y));
    __syncthreads();

    int i0 = rb * 128 + t;
    int i1 = i0 + 64;
    float4 b0 = (i0 < PRE_K) ? g_nboxes[i0] : make_float4(0.f, 0.f, 0.f, 0.f);
    float4 b1 = (i1 < PRE_K) ? g_nboxes[i1] : make_float4(0.f, 0.f, 0.f, 0.f);
    float a0 = __fmul_rn(__fsub_rn(b0.z, b0.x), __fsub_rn(b0.w, b0.y));
    float a1 = __fmul_rn(__fsub_rn(b1.z, b1.x), __fsub_rn(b1.w, b1.y));

    u64 bits0 = 0ull, bits1 = 0ull;
    int cmax = PRE_K - cb * 64; if (cmax > 64) cmax = 64;
    for (int c = 0; c < cmax; ++c) {
        float4 bc = sb[c];
        float ac = sa[c];
        {
            float lx = fmaxf(b0.x, bc.x), ly = fmaxf(b0.y, bc.y);
            float rx = fminf(b0.z, bc.z), ry = fminf(b0.w, bc.w);
            float w = fmaxf(__fsub_rn(rx, lx), 0.f);
            float h = fmaxf(__fsub_rn(ry, ly), 0.f);
            float inter = __fmul_rn(w, h);
            float denom = __fsub_rn(__fadd_rn(a0, ac), inter);
            float iou = inter / denom;
            if (iou > 0.7f) bits0 |= (1ull << c);
        }
        {
            float lx = fmaxf(b1.x, bc.x), ly = fmaxf(b1.y, bc.y);
            float rx = fminf(b1.z, bc.z), ry = fminf(b1.w, bc.w);
            float w = fmaxf(__fsub_rn(rx, lx), 0.f);
            float h = fmaxf(__fsub_rn(ry, ly), 0.f);
            float inter = __fmul_rn(w, h);
            float denom = __fsub_rn(__fadd_rn(a1, ac), inter);
            float iou = inter / denom;
            if (iou > 0.7f) bits1 |= (1ull << c);
        }
    }
    if (i0 < PRE_K) g_mask[(size_t)i0 * NWP + cb] = bits0;
    if (i1 < PRE_K) g_mask[(size_t)i1 * NWP + cb] = bits1;
}

/* ---------------- K7: single-warp greedy NMS scan ------------------------ */
/* Chain skips non-candidate bits (cost ~ kept rows, not 64/block); fold is
   4-row unrolled and skips words <= current block (never read again).      */
__global__ void nms_scan_kernel() {
    const unsigned FULL = 0xffffffffu;
    int lane = threadIdx.x;
    int w0 = 3 * lane;                  /* lane 31: 93,94,95 (pads zero) */
    u64 rm0 = 0, rm1 = 0, rm2 = 0;
    u64 tv0 = g_tvalid[w0 + 0];
    u64 tv1 = g_tvalid[w0 + 1];
    u64 tv2 = g_tvalid[w0 + 2];
    int kept_total = 0;

    for (int c = 0; c < NW; ++c) {
        int owner = c / 3;
        int slot  = c - 3 * owner;
        u64 myrem = (slot == 0) ? rm0 : ((slot == 1) ? rm1 : rm2);
        u64 mytv  = (slot == 0) ? tv0 : ((slot == 1) ? tv1 : tv2);
        u64 rem_c = __shfl_sync(FULL, myrem, owner);
        u64 tv_c  = __shfl_sync(FULL, mytv,  owner);

        int r0 = c * 64 + 2 * lane;
        u64 m0 = (r0     < PRE_K) ? g_mask[(size_t)r0       * NWP + c] : 0ull;
        u64 m1 = (r0 + 1 < PRE_K) ? g_mask[(size_t)(r0 + 1) * NWP + c] : 0ull;

        /* greedy chain over candidate bits only (uniform across lanes) */
        u64 local = rem_c, keptmask = 0ull;
        u64 mb = tv_c & ~local;
        while (mb) {
            int k = __ffsll((long long)mb) - 1;
            u64 v = __shfl_sync(FULL, (k & 1) ? m1 : m0, k >> 1);
            keptmask |= (1ull << k);
            local |= v;
            mb = tv_c & ~local & ~((2ull << k) - 1ull);  /* bits > k */
        }

        if (lane == 0) g_keep[c] = keptmask;
        kept_total += __popcll(keptmask);
        if (kept_total >= POST_K) break;     /* later ranks never emitted */

        /* fold kept rows into per-lane removed words (4-row unroll).
           Words <= c are never consulted again -> lanes fully below skip. */
        if (w0 + 2 > c) {
            u64 mbf = keptmask;
            while (mbf) {
                int kA = __ffsll((long long)mbf) - 1; mbf &= mbf - 1;
                int kB = -1, kC = -1, kD = -1;
                if (mbf) { kB = __ffsll((long long)mbf) - 1; mbf &= mbf - 1; }
                if (mbf) { kC = __ffsll((long long)mbf) - 1; mbf &= mbf - 1; }
                if (mbf) { kD = __ffsll((long long)mbf) - 1; mbf &= mbf - 1; }
                const u64* pA = &g_mask[(size_t)(c * 64 + kA) * NWP + w0];
                u64 o0 = pA[0], o1 = pA[1], o2 = pA[2];
                if (kB >= 0) { const u64* p = &g_mask[(size_t)(c * 64 + kB) * NWP + w0];
                               o0 |= p[0]; o1 |= p[1]; o2 |= p[2]; }
                if (kC >= 0) { const u64* p = &g_mask[(size_t)(c * 64 + kC) * NWP + w0];
                               o0 |= p[0]; o1 |= p[1]; o2 |= p[2]; }
                if (kD >= 0) { const u64* p = &g_mask[(size_t)(c * 64 + kD) * NWP + w0];
                               o0 |= p[0]; o1 |= p[1]; o2 |= p[2]; }
                rm0 |= o0; rm1 |= o1; rm2 |= o2;
            }
        }
    }
}

/* ---------------- K8: emit first 300 kept rows ---------------- */
__global__ void output_kernel(float* __restrict__ out) {
    __shared__ u64 skeep[NW];
    __shared__ int spref[NW];
    int t = threadIdx.x;
    for (int i = t; i < POST_K * 5; i += 512) out[i] = 0.f;
    if (t < NW) skeep[t] = g_keep[t];
    __syncthreads();
    if (t == 0) {
        int run = 0;
        for (int w = 0; w < NW; ++w) { spref[w] = run; run += __popcll(skeep[w]); }
    }
    __syncthreads();
    for (int i = t; i < PRE_K; i += 512) {
        int w = i >> 6, b = i & 63;
        u64 kw = skeep[w];
        if ((kw >> b) & 1ull) {
            u64 lowmask = (b == 0) ? 0ull : ((~0ull) >> (64 - b));
            int rank = spref[w] + __popcll(kw & lowmask);
            if (rank < POST_K) {
                float4 bx = g_nboxes[i];
                out[rank * 5 + 1] = bx.x;
                out[rank * 5 + 2] = bx.y;
                out[rank * 5 + 3] = bx.z;
                out[rank * 5 + 4] = bx.w;
            }
        }
    }
}

/* ---------------- launch ---------------- */
extern "C" void kernel_launch(void* const* d_in, const int* in_sizes, int n_in,
                              void* d_out, int out_size) {
    const float* scores = (const float*)d_in[0];
    const float* deltas = (const float*)d_in[1];
    const float* iminfo = (const float*)d_in[2];
    float* out = (float*)d_out;

    zero_kernel<<<(ZERO_ITEMS + 255) / 256, 256>>>();
    decode_kernel<<<NTOT / 256, 256>>>(scores, deltas, iminfo);
    thresh_kernel<<<1, 1024>>>();
    compact_kernel<<<NTOT / 256, 256>>>();
    rank_kernel<<<SORT_CAP / 128, 128>>>();
    gather_kernel<<<NW, 64>>>();
    iou_kernel<<<dim3(NW, (PRE_K + 127) / 128), 64>>>();
    nms_scan_kernel<<<1, 32>>>();
    output_kernel<<<1, 512>>>(out);
}

// round 4
// speedup vs baseline: 1.6306x; 1.3594x over previous
#include <cuda_runtime.h>
#include <math.h>

typedef unsigned long long u64;
typedef unsigned int u32;

#define HH 128
#define WW 192
#define NA 9
#define NTOT (HH*WW*NA)      /* 221184 */
#define HW   (HH*WW)
#define PRE_K 6000
#define POST_K 300
#define NW 94                /* ceil(6000/64) */
#define NWP 96               /* padded row stride (u64 words) */
#define NBINS 65536
#define SORT_CAP 8192
#define NSEG 8               /* rank counting segments */

/* ---------------- scratch (no allocation allowed) ---------------- */
__device__ float4 g_boxes[NTOT];       /* (a, sp) layout */
__device__ u32    g_key[NTOT];         /* (a, sp) layout */
__device__ __align__(16) u32 g_hist[NBINS];
__device__ u32    g_threshbin;
__device__ u32    g_candcount;
__device__ u64    g_cand[SORT_CAP];
__device__ u32    g_rankp[NSEG * SORT_CAP];
__device__ u64    g_srt[PRE_K];
__device__ float4 g_nboxes[PRE_K];
__device__ u64    g_tvalid[NWP];
__device__ u64    g_mask[(size_t)PRE_K * NWP];   /* 4.6 MB, padded words zero */
__device__ u64    g_keep[NWP];

/* anchors from _generate_anchors(16,(.5,1,2),(8,16,32)) */
__constant__ float c_anch[NA][4] = {
    {-84.f,  -40.f,  99.f,  55.f},
    {-176.f, -88.f,  191.f, 103.f},
    {-360.f, -184.f, 375.f, 199.f},
    {-56.f,  -56.f,  71.f,  71.f},
    {-120.f, -120.f, 135.f, 135.f},
    {-248.f, -248.f, 263.f, 263.f},
    {-36.f,  -80.f,  51.f,  95.f},
    {-80.f,  -168.f, 95.f,  183.f},
    {-168.f, -344.f, 183.f, 359.f}
};

/* ---------------- K0: zero/init scratch ---------------- */
__global__ void zero_kernel() {
    int i = blockIdx.x * 256 + threadIdx.x;
    if (i < NBINS) { g_hist[i] = 0u; return; }
    int j = i - NBINS;
    if (j < NWP) { g_tvalid[j] = 0ull; return; }
    j -= NWP;
    if (j < NWP) { g_keep[j] = 0ull; return; }
    j -= NWP;
    if (j < 2) { if (j == 0) g_candcount = 0u; else g_threshbin = NBINS - 1; return; }
    j -= 2;
    if (j < SORT_CAP) { g_cand[j] = ~0ull; return; }
    j -= SORT_CAP;
    if (j < PRE_K * 2) {      /* zero pad words 94,95 of every mask row */
        int r = j >> 1;
        g_mask[(size_t)r * NWP + NW + (j & 1)] = 0ull;
    }
}
#define ZERO_ITEMS (NBINS + 2*NWP + 2 + SORT_CAP + PRE_K*2)

/* ---------------- K1: decode + score key + histogram (coalesced) --------- */
__global__ void decode_kernel(const float* __restrict__ scores,
                              const float* __restrict__ deltas,
                              const float* __restrict__ iminfo) {
    int tid = blockIdx.x * 256 + threadIdx.x;     /* grid covers NTOT exactly */
    int a  = tid / HW;
    int sp = tid - a * HW;
    int y  = sp / WW;
    int x  = sp - y * WW;

    float sx = 16.f * (float)x;
    float sy = 16.f * (float)y;
    float ax1 = c_anch[a][0] + sx;
    float ay1 = c_anch[a][1] + sy;
    float aw  = (c_anch[a][2] - c_anch[a][0]) + 1.f;
    float ah  = (c_anch[a][3] - c_anch[a][1]) + 1.f;
    float cx  = __fadd_rn(ax1, 0.5f * aw);
    float cy  = __fadd_rn(ay1, 0.5f * ah);

    float dx = deltas[(4*a+0)*HW + sp];
    float dy = deltas[(4*a+1)*HW + sp];
    float dw = fminf(fmaxf(deltas[(4*a+2)*HW + sp], -10.f), 10.f);
    float dh = fminf(fmaxf(deltas[(4*a+3)*HW + sp], -10.f), 10.f);

    float pcx = __fadd_rn(__fmul_rn(dx, aw), cx);
    float pcy = __fadd_rn(__fmul_rn(dy, ah), cy);
    float pw  = __fmul_rn(expf(dw), aw);
    float ph  = __fmul_rn(expf(dh), ah);
    float hx  = __fmul_rn(0.5f, pw);
    float hy  = __fmul_rn(0.5f, ph);
    float x1 = __fsub_rn(pcx, hx), x2 = __fadd_rn(pcx, hx);
    float y1 = __fsub_rn(pcy, hy), y2 = __fadd_rn(pcy, hy);

    float xmax = __fsub_rn(iminfo[1], 1.f);
    float ymax = __fsub_rn(iminfo[0], 1.f);
    x1 = fminf(fmaxf(x1, 0.f), xmax);
    x2 = fminf(fmaxf(x2, 0.f), xmax);
    y1 = fminf(fmaxf(y1, 0.f), ymax);
    y2 = fminf(fmaxf(y2, 0.f), ymax);

    float minsz = __fmul_rn(16.f, iminfo[2]);
    bool valid = (__fadd_rn(__fsub_rn(x2, x1), 1.f) >= minsz) &&
                 (__fadd_rn(__fsub_rn(y2, y1), 1.f) >= minsz);

    float sc = scores[(NA + a)*HW + sp];
    u32 u = valid ? __float_as_uint(sc) : 0xFF800000u;
    u32 m = (u & 0x80000000u) ? ~u : (u | 0x80000000u);
    u32 key = ~m;                                  /* big score -> small key */

    g_boxes[tid] = make_float4(x1, y1, x2, y2);
    g_key[tid]   = key;
    atomicAdd(&g_hist[key >> 16], 1u);
}

/* ---------------- K2: find threshold bin ---------------- */
__global__ void thresh_kernel() {
    __shared__ u32 ss[1024];
    int t = threadIdx.x;
    int base = t * 64;
    u32 v = 0;
    const uint4* h4 = (const uint4*)&g_hist[base];
    #pragma unroll 16
    for (int b = 0; b < 16; b++) {
        uint4 q = h4[b];
        v += q.x + q.y + q.z + q.w;
    }
    ss[t] = v;
    __syncthreads();
    for (int off = 1; off < 1024; off <<= 1) {
        u32 x = (t >= off) ? ss[t - off] : 0u;
        __syncthreads();
        ss[t] += x;
        __syncthreads();
    }
    u32 incl = ss[t], excl = incl - v;
    if (excl < PRE_K && incl >= PRE_K) {
        u32 cum = excl;
        for (int b = 0; b < 64; b++) {
            cum += g_hist[base + b];
            if (cum >= PRE_K) { g_threshbin = (u32)(base + b); break; }
        }
    }
}

/* ---------------- K3: compact candidates (block-aggregated atomic) ------- */
__global__ void compact_kernel() {
    __shared__ u32 sbase;
    __shared__ u32 scnt;
    int tid = blockIdx.x * 256 + threadIdx.x;
    if (threadIdx.x == 0) scnt = 0u;
    __syncthreads();
    u32 key = g_key[tid];
    bool sel = (key >> 16) <= g_threshbin;
    u32 pos = 0;
    if (sel) pos = atomicAdd(&scnt, 1u);
    __syncthreads();
    if (threadIdx.x == 0) sbase = atomicAdd(&g_candcount, scnt);
    __syncthreads();
    if (sel) {
        int a = tid / HW, sp = tid - a * HW;
        u32 orig = (u32)(sp * NA + a);             /* reference ordering idx */
        u32 p = sbase + pos;
        if (p < SORT_CAP) g_cand[p] = ((u64)key << 32) | orig;
    }
}

/* ---------------- K4a: partial rank counting (8x parallel) --------------- */
__global__ void rank_count_kernel() {
    __shared__ u64 tile[1024];
    int t = threadIdx.x;                           /* 128 */
    int item = blockIdx.x * 128 + t;
    u64 mine = g_cand[item];
    int base = blockIdx.y * 1024;
    #pragma unroll
    for (int i = 0; i < 8; i++) tile[t + i * 128] = g_cand[base + t + i * 128];
    __syncthreads();
    u32 r = 0;
    #pragma unroll 16
    for (int i = 0; i < 1024; i++) r += (tile[i] < mine) ? 1u : 0u;
    g_rankp[blockIdx.y * SORT_CAP + item] = r;
}

/* ---------------- K4b: scatter to sorted order --------------------------- */
__global__ void rank_scatter_kernel() {
    int i = blockIdx.x * 256 + threadIdx.x;
    u32 r = 0;
    #pragma unroll
    for (int s = 0; s < NSEG; s++) r += g_rankp[s * SORT_CAP + i];
    if (r < PRE_K) g_srt[r] = g_cand[i];
}

/* ---------------- K5: gather top-6000 boxes + validity bits -------------- */
__global__ void gather_kernel() {
    int c = blockIdx.x;          /* NW blocks */
    int t = threadIdx.x;         /* 64 */
    int j = c * 64 + t;
    bool valid = false;
    if (j < PRE_K) {
        u64 v = g_srt[j];
        u32 key = (u32)(v >> 32);
        valid = key < 0xFF800000u;
        u32 orig = (u32)v;
        int aa = orig % NA;
        int sp = orig / NA;
        g_nboxes[j] = g_boxes[aa * HW + sp];
    }
    u32 b = __ballot_sync(0xffffffffu, valid);
    if ((t & 31) == 0) atomicOr(&g_tvalid[c], ((u64)b) << ((t >> 5) * 32));
}

/* ---------------- K6: IoU bitmask, UPPER TRIANGLE only ------------------- */
/* Consumer (nms scan) only reads mask[r][c] with c >= r/64: the chain reads
   diagonal blocks, the fold reads words >= current block, and rem words
   below the current block are dead.  Skip all lower-triangle blocks.       */
__global__ void iou_kernel() {
    __shared__ float4 sb[64];
    __shared__ float  sa[64];
    int cb = blockIdx.x, rb = blockIdx.y, t = threadIdx.x;   /* 64 threads */
    if (cb < 2 * rb) return;          /* whole block in lower triangle */
    int j = cb * 64 + t;
    float4 bj = (j < PRE_K) ? g_nboxes[j] : make_float4(0.f, 0.f, 0.f, 0.f);
    sb[t] = bj;
    sa[t] = __fmul_rn(__fsub_rn(bj.z, bj.x), __fsub_rn(bj.w, bj.y));
    __syncthreads();

    int i0 = rb * 128 + t;
    int i1 = i0 + 64;
    bool do1 = (cb >= 2 * rb + 1);
    float4 b0 = (i0 < PRE_K) ? g_nboxes[i0] : make_float4(0.f, 0.f, 0.f, 0.f);
    float4 b1 = (do1 && i1 < PRE_K) ? g_nboxes[i1] : make_float4(0.f, 0.f, 0.f, 0.f);
    float a0 = __fmul_rn(__fsub_rn(b0.z, b0.x), __fsub_rn(b0.w, b0.y));
    float a1 = __fmul_rn(__fsub_rn(b1.z, b1.x), __fsub_rn(b1.w, b1.y));

    u64 bits0 = 0ull, bits1 = 0ull;
    int cmax = PRE_K - cb * 64; if (cmax > 64) cmax = 64;
    for (int c = 0; c < cmax; ++c) {
        float4 bc = sb[c];
        float ac = sa[c];
        {
            float lx = fmaxf(b0.x, bc.x), ly = fmaxf(b0.y, bc.y);
            float rx = fminf(b0.z, bc.z), ry = fminf(b0.w, bc.w);
            float w = fmaxf(__fsub_rn(rx, lx), 0.f);
            float h = fmaxf(__fsub_rn(ry, ly), 0.f);
            float inter = __fmul_rn(w, h);
            float denom = __fsub_rn(__fadd_rn(a0, ac), inter);
            float iou = inter / denom;
            if (iou > 0.7f) bits0 |= (1ull << c);
        }
        {
            float lx = fmaxf(b1.x, bc.x), ly = fmaxf(b1.y, bc.y);
            float rx = fminf(b1.z, bc.z), ry = fminf(b1.w, bc.w);
            float w = fmaxf(__fsub_rn(rx, lx), 0.f);
            float h = fmaxf(__fsub_rn(ry, ly), 0.f);
            float inter = __fmul_rn(w, h);
            float denom = __fsub_rn(__fadd_rn(a1, ac), inter);
            float iou = inter / denom;
            if (iou > 0.7f) bits1 |= (1ull << c);
        }
    }
    if (i0 < PRE_K) g_mask[(size_t)i0 * NWP + cb] = bits0;
    if (do1 && i1 < PRE_K) g_mask[(size_t)i1 * NWP + cb] = bits1;
}

/* ---------------- K7: single-warp greedy NMS scan ------------------------ */
__global__ void nms_scan_kernel() {
    const unsigned FULL = 0xffffffffu;
    int lane = threadIdx.x;
    int w0 = 3 * lane;                  /* lane 31: 93,94,95 (pads zero) */
    u64 rm0 = 0, rm1 = 0, rm2 = 0;
    u64 tv0 = g_tvalid[w0 + 0];
    u64 tv1 = g_tvalid[w0 + 1];
    u64 tv2 = g_tvalid[w0 + 2];
    int kept_total = 0;

    /* preload diagonal words for block 0 */
    int pr = 2 * lane;
    u64 m0 = g_mask[(size_t)pr * NWP + 0];
    u64 m1 = g_mask[(size_t)(pr + 1) * NWP + 0];

    for (int c = 0; c < NW; ++c) {
        /* prefetch next block's diagonal words (hidden behind chain) */
        u64 n0 = 0ull, n1 = 0ull;
        if (c + 1 < NW) {
            int rr = (c + 1) * 64 + 2 * lane;
            if (rr     < PRE_K) n0 = g_mask[(size_t)rr       * NWP + (c + 1)];
            if (rr + 1 < PRE_K) n1 = g_mask[(size_t)(rr + 1) * NWP + (c + 1)];
        }

        int owner = c / 3;
        int slot  = c - 3 * owner;
        u64 myrem = (slot == 0) ? rm0 : ((slot == 1) ? rm1 : rm2);
        u64 mytv  = (slot == 0) ? tv0 : ((slot == 1) ? tv1 : tv2);
        u64 rem_c = __shfl_sync(FULL, myrem, owner);
        u64 tv_c  = __shfl_sync(FULL, mytv,  owner);

        /* greedy chain over candidate bits only (uniform across lanes) */
        u64 local = rem_c, keptmask = 0ull;
        u64 mb = tv_c & ~local;
        while (mb) {
            int k = __ffsll((long long)mb) - 1;
            u64 v = __shfl_sync(FULL, (k & 1) ? m1 : m0, k >> 1);
            keptmask |= (1ull << k);
            local |= v;
            mb = tv_c & ~local & ~((2ull << k) - 1ull);  /* bits > k */
        }

        if (lane == 0) g_keep[c] = keptmask;
        kept_total += __popcll(keptmask);
        if (kept_total >= POST_K) break;     /* later ranks never emitted */

        /* fold kept rows into per-lane removed words, 8 rows per batch
           (MLP 24).  Words <= c never consulted again -> lanes below skip. */
        if (w0 + 2 > c) {
            u64 mbf = keptmask;
            while (mbf) {
                int rk[8]; int rcnt = 0;
                #pragma unroll
                for (int q = 0; q < 8; q++) {
                    if (mbf) {
                        rk[q] = __ffsll((long long)mbf) - 1;
                        mbf &= mbf - 1;
                        rcnt = q + 1;
                    } else rk[q] = -1;
                }
                u64 o0 = 0ull, o1 = 0ull, o2 = 0ull;
                #pragma unroll
                for (int q = 0; q < 8; q++) {
                    if (rk[q] >= 0) {
                        const u64* p = &g_mask[(size_t)(c * 64 + rk[q]) * NWP + w0];
                        o0 |= p[0]; o1 |= p[1]; o2 |= p[2];
                    }
                }
                (void)rcnt;
                rm0 |= o0; rm1 |= o1; rm2 |= o2;
            }
        }
        m0 = n0; m1 = n1;
    }
}

/* ---------------- K8: emit first 300 kept rows ---------------- */
__global__ void output_kernel(float* __restrict__ out) {
    __shared__ u64 skeep[NW];
    __shared__ int spref[NW];
    int t = threadIdx.x;
    for (int i = t; i < POST_K * 5; i += 512) out[i] = 0.f;
    if (t < NW) skeep[t] = g_keep[t];
    __syncthreads();
    if (t == 0) {
        int run = 0;
        for (int w = 0; w < NW; ++w) { spref[w] = run; run += __popcll(skeep[w]); }
    }
    __syncthreads();
    for (int i = t; i < PRE_K; i += 512) {
        int w = i >> 6, b = i & 63;
        u64 kw = skeep[w];
        if ((kw >> b) & 1ull) {
            u64 lowmask = (b == 0) ? 0ull : ((~0ull) >> (64 - b));
            int rank = spref[w] + __popcll(kw & lowmask);
            if (rank < POST_K) {
                float4 bx = g_nboxes[i];
                out[rank * 5 + 1] = bx.x;
                out[rank * 5 + 2] = bx.y;
                out[rank * 5 + 3] = bx.z;
                out[rank * 5 + 4] = bx.w;
            }
        }
    }
}

/* ---------------- launch ---------------- */
extern "C" void kernel_launch(void* const* d_in, const int* in_sizes, int n_in,
                              void* d_out, int out_size) {
    const float* scores = (const float*)d_in[0];
    const float* deltas = (const float*)d_in[1];
    const float* iminfo = (const float*)d_in[2];
    float* out = (float*)d_out;

    zero_kernel<<<(ZERO_ITEMS + 255) / 256, 256>>>();
    decode_kernel<<<NTOT / 256, 256>>>(scores, deltas, iminfo);
    thresh_kernel<<<1, 1024>>>();
    compact_kernel<<<NTOT / 256, 256>>>();
    rank_count_kernel<<<dim3(SORT_CAP / 128, NSEG), 128>>>();
    rank_scatter_kernel<<<SORT_CAP / 256, 256>>>();
    gather_kernel<<<NW, 64>>>();
    iou_kernel<<<dim3(NW, (PRE_K + 127) / 128), 64>>>();
    nms_scan_kernel<<<1, 32>>>();
    output_kernel<<<1, 512>>>(out);
}

// round 5
// speedup vs baseline: 1.6853x; 1.0335x over previous
#include <cuda_runtime.h>
#include <math.h>

typedef unsigned long long u64;
typedef unsigned int u32;

#define HH 128
#define WW 192
#define NA 9
#define NTOT (HH*WW*NA)      /* 221184 */
#define HW   (HH*WW)
#define PRE_K 6000
#define POST_K 300
#define NW 94                /* ceil(6000/64) */
#define NWP 96               /* padded row stride (u64 words) */
#define NBINS 65536
#define SORT_CAP 8192
#define NSEG 16
#define TSEG (SORT_CAP/NSEG) /* 512 */

/* ---------------- scratch (no allocation allowed) ---------------- */
__device__ float4 g_boxes[NTOT];       /* (a, sp) layout */
__device__ __align__(16) u32 g_key[NTOT];
__device__ __align__(16) u32 g_hist[NBINS];
__device__ u32    g_threshbin;
__device__ u32    g_candcount;
__device__ u64    g_cand[SORT_CAP];
__device__ u32    g_rankp[NSEG * SORT_CAP];
__device__ float4 g_nboxes[PRE_K];
__device__ u64    g_tvalid[NW];
__device__ u64    g_mask[(size_t)PRE_K * NWP];   /* 4.6 MB */

/* anchors from _generate_anchors(16,(.5,1,2),(8,16,32)) */
__constant__ float c_anch[NA][4] = {
    {-84.f,  -40.f,  99.f,  55.f},
    {-176.f, -88.f,  191.f, 103.f},
    {-360.f, -184.f, 375.f, 199.f},
    {-56.f,  -56.f,  71.f,  71.f},
    {-120.f, -120.f, 135.f, 135.f},
    {-248.f, -248.f, 263.f, 263.f},
    {-36.f,  -80.f,  51.f,  95.f},
    {-80.f,  -168.f, 95.f,  183.f},
    {-168.f, -344.f, 183.f, 359.f}
};

/* ---------------- K0: init scratch (slim) ---------------- */
__global__ void init_kernel() {
    int i = blockIdx.x * 256 + threadIdx.x;
    if (i < NBINS / 4) { ((uint4*)g_hist)[i] = make_uint4(0u, 0u, 0u, 0u); return; }
    int j = i - NBINS / 4;
    if (j < NW) { g_tvalid[j] = 0ull; return; }
    j -= NW;
    if (j == 0) g_candcount = 0u;
}
#define INIT_ITEMS (NBINS/4 + NW + 1)

/* ---------------- K1: decode + score key + histogram (coalesced) --------- */
__global__ void decode_kernel(const float* __restrict__ scores,
                              const float* __restrict__ deltas,
                              const float* __restrict__ iminfo) {
    int tid = blockIdx.x * 256 + threadIdx.x;     /* grid covers NTOT exactly */
    int a  = tid / HW;
    int sp = tid - a * HW;
    int y  = sp / WW;
    int x  = sp - y * WW;

    float sx = 16.f * (float)x;
    float sy = 16.f * (float)y;
    float ax1 = c_anch[a][0] + sx;
    float ay1 = c_anch[a][1] + sy;
    float aw  = (c_anch[a][2] - c_anch[a][0]) + 1.f;
    float ah  = (c_anch[a][3] - c_anch[a][1]) + 1.f;
    float cx  = __fadd_rn(ax1, 0.5f * aw);
    float cy  = __fadd_rn(ay1, 0.5f * ah);

    float dx = deltas[(4*a+0)*HW + sp];
    float dy = deltas[(4*a+1)*HW + sp];
    float dw = fminf(fmaxf(deltas[(4*a+2)*HW + sp], -10.f), 10.f);
    float dh = fminf(fmaxf(deltas[(4*a+3)*HW + sp], -10.f), 10.f);

    float pcx = __fadd_rn(__fmul_rn(dx, aw), cx);
    float pcy = __fadd_rn(__fmul_rn(dy, ah), cy);
    float pw  = __fmul_rn(expf(dw), aw);
    float ph  = __fmul_rn(expf(dh), ah);
    float hx  = __fmul_rn(0.5f, pw);
    float hy  = __fmul_rn(0.5f, ph);
    float x1 = __fsub_rn(pcx, hx), x2 = __fadd_rn(pcx, hx);
    float y1 = __fsub_rn(pcy, hy), y2 = __fadd_rn(pcy, hy);

    float xmax = __fsub_rn(iminfo[1], 1.f);
    float ymax = __fsub_rn(iminfo[0], 1.f);
    x1 = fminf(fmaxf(x1, 0.f), xmax);
    x2 = fminf(fmaxf(x2, 0.f), xmax);
    y1 = fminf(fmaxf(y1, 0.f), ymax);
    y2 = fminf(fmaxf(y2, 0.f), ymax);

    float minsz = __fmul_rn(16.f, iminfo[2]);
    bool valid = (__fadd_rn(__fsub_rn(x2, x1), 1.f) >= minsz) &&
                 (__fadd_rn(__fsub_rn(y2, y1), 1.f) >= minsz);

    float sc = scores[(NA + a)*HW + sp];
    u32 u = valid ? __float_as_uint(sc) : 0xFF800000u;
    u32 m = (u & 0x80000000u) ? ~u : (u | 0x80000000u);
    u32 key = ~m;                                  /* big score -> small key */

    g_boxes[tid] = make_float4(x1, y1, x2, y2);
    g_key[tid]   = key;
    atomicAdd(&g_hist[key >> 16], 1u);
}

/* ---------------- K2: find threshold bin ---------------- */
__global__ void thresh_kernel() {
    __shared__ u32 ss[1024];
    int t = threadIdx.x;
    int base = t * 64;
    u32 v = 0;
    const uint4* h4 = (const uint4*)&g_hist[base];
    #pragma unroll 16
    for (int b = 0; b < 16; b++) {
        uint4 q = h4[b];
        v += q.x + q.y + q.z + q.w;
    }
    ss[t] = v;
    __syncthreads();
    for (int off = 1; off < 1024; off <<= 1) {
        u32 x = (t >= off) ? ss[t - off] : 0u;
        __syncthreads();
        ss[t] += x;
        __syncthreads();
    }
    u32 incl = ss[t], excl = incl - v;
    if (excl < PRE_K && incl >= PRE_K) {
        u32 cum = excl;
        for (int b = 0; b < 64; b++) {
            cum += g_hist[base + b];
            if (cum >= PRE_K) { g_threshbin = (u32)(base + b); break; }
        }
    }
}

/* ---------------- K3: compact candidates (uint4 keys, block atomic) ------ */
__global__ void compact_kernel() {
    __shared__ u32 sbase;
    __shared__ u32 scnt;
    int tid = blockIdx.x * 256 + threadIdx.x;      /* covers NTOT/4 exactly */
    if (threadIdx.x == 0) scnt = 0u;
    __syncthreads();
    uint4 k4 = ((const uint4*)g_key)[tid];
    u32 tb = g_threshbin;
    u32 ks0 = k4.x, ks1 = k4.y, ks2 = k4.z, ks3 = k4.w;
    int n = ((ks0 >> 16) <= tb) + ((ks1 >> 16) <= tb) +
            ((ks2 >> 16) <= tb) + ((ks3 >> 16) <= tb);
    u32 pos = 0;
    if (n) pos = atomicAdd(&scnt, (u32)n);
    __syncthreads();
    if (threadIdx.x == 0) sbase = atomicAdd(&g_candcount, scnt);
    __syncthreads();
    if (n) {
        int i0 = tid * 4;
        int a = i0 / HW, spb = i0 - a * HW;        /* uint4 never crosses a-plane */
        u32 base = sbase + pos;
        u32 ks[4] = {ks0, ks1, ks2, ks3};
        #pragma unroll
        for (int e = 0; e < 4; e++) {
            if ((ks[e] >> 16) <= tb) {
                u32 orig = (u32)((spb + e) * NA + a);
                if (base < SORT_CAP) g_cand[base] = ((u64)ks[e] << 32) | orig;
                base++;
            }
        }
    }
}

/* ---------------- K4a: partial rank counting (4 items/thread) ------------ */
__global__ void rank_count_kernel() {
    __shared__ u64 tile[TSEG];
    int t = threadIdx.x;                           /* 128 */
    u32 cnt = g_candcount; if (cnt > SORT_CAP) cnt = SORT_CAP;
    int segbase = blockIdx.y * TSEG;
    for (int i = t; i < TSEG; i += 128) {
        int idx = segbase + i;
        tile[i] = (idx < (int)cnt) ? g_cand[idx] : ~0ull;
    }
    int ib = blockIdx.x * 512;
    int i0 = ib + t, i1 = i0 + 128, i2 = i0 + 256, i3 = i0 + 384;
    u64 m0 = (i0 < (int)cnt) ? g_cand[i0] : ~0ull;
    u64 m1 = (i1 < (int)cnt) ? g_cand[i1] : ~0ull;
    u64 m2 = (i2 < (int)cnt) ? g_cand[i2] : ~0ull;
    u64 m3 = (i3 < (int)cnt) ? g_cand[i3] : ~0ull;
    __syncthreads();
    u32 r0 = 0, r1 = 0, r2 = 0, r3 = 0;
    #pragma unroll 8
    for (int i = 0; i < TSEG; i++) {
        u64 v = tile[i];
        r0 += (v < m0) ? 1u : 0u;
        r1 += (v < m1) ? 1u : 0u;
        r2 += (v < m2) ? 1u : 0u;
        r3 += (v < m3) ? 1u : 0u;
    }
    u32* dst = &g_rankp[blockIdx.y * SORT_CAP];
    dst[i0] = r0; dst[i1] = r1; dst[i2] = r2; dst[i3] = r3;
}

/* ---------------- K4b: scatter + gather fused ---------------------------- */
__global__ void scatter_gather_kernel() {
    int i = blockIdx.x * 256 + threadIdx.x;        /* covers SORT_CAP */
    u32 cnt = g_candcount; if (cnt > SORT_CAP) cnt = SORT_CAP;
    u32 r = 0;
    #pragma unroll
    for (int s = 0; s < NSEG; s++) r += g_rankp[s * SORT_CAP + i];
    if (i < (int)cnt && r < PRE_K) {
        u64 v = g_cand[i];
        u32 key  = (u32)(v >> 32);
        u32 orig = (u32)v;
        int aa = orig % NA;
        int sp = orig / NA;
        g_nboxes[r] = g_boxes[aa * HW + sp];
        if (key < 0xFF800000u)
            atomicOr(&g_tvalid[r >> 6], 1ull << (r & 63));
    }
}

/* ---------------- K6: IoU bitmask, upper triangle, margin-division ------- */
__global__ void iou_kernel() {
    __shared__ float4 sb[64];
    __shared__ float  sa[64];
    int cb = blockIdx.x, rb = blockIdx.y, t = threadIdx.x;   /* 64 threads */
    if (cb < 2 * rb) return;
    int j = cb * 64 + t;
    float4 bj = (j < PRE_K) ? g_nboxes[j] : make_float4(0.f, 0.f, 0.f, 0.f);
    sb[t] = bj;
    sa[t] = __fmul_rn(__fsub_rn(bj.z, bj.x), __fsub_rn(bj.w, bj.y));
    __syncthreads();

    int i0 = rb * 128 + t;
    int i1 = i0 + 64;
    bool do1 = (cb >= 2 * rb + 1);
    float4 b0 = (i0 < PRE_K) ? g_nboxes[i0] : make_float4(0.f, 0.f, 0.f, 0.f);
    float4 b1 = (do1 && i1 < PRE_K) ? g_nboxes[i1] : make_float4(0.f, 0.f, 0.f, 0.f);
    float a0 = __fmul_rn(__fsub_rn(b0.z, b0.x), __fsub_rn(b0.w, b0.y));
    float a1 = __fmul_rn(__fsub_rn(b1.z, b1.x), __fsub_rn(b1.w, b1.y));

    u64 bits0 = 0ull, bits1 = 0ull;
    int cmax = PRE_K - cb * 64; if (cmax > 64) cmax = 64;
    for (int c = 0; c < cmax; ++c) {
        float4 bc = sb[c];
        float ac = sa[c];
        {
            float lx = fmaxf(b0.x, bc.x), ly = fmaxf(b0.y, bc.y);
            float rx = fminf(b0.z, bc.z), ry = fminf(b0.w, bc.w);
            float w = fmaxf(__fsub_rn(rx, lx), 0.f);
            float h = fmaxf(__fsub_rn(ry, ly), 0.f);
            float inter = __fmul_rn(w, h);
            float denom = __fsub_rn(__fadd_rn(a0, ac), inter);
            /* decision-exact: |d| >= 1e-6*denom decides sign of (iou-0.7) */
            float d = __fmaf_rn(-0.7f, denom, inter);
            bool dec = d > 0.f;
            if (fabsf(d) < 1e-6f * denom) dec = (inter / denom) > 0.7f;
            if (dec) bits0 |= (1ull << c);
        }
        {
            float lx = fmaxf(b1.x, bc.x), ly = fmaxf(b1.y, bc.y);
            float rx = fminf(b1.z, bc.z), ry = fminf(b1.w, bc.w);
            float w = fmaxf(__fsub_rn(rx, lx), 0.f);
            float h = fmaxf(__fsub_rn(ry, ly), 0.f);
            float inter = __fmul_rn(w, h);
            float denom = __fsub_rn(__fadd_rn(a1, ac), inter);
            float d = __fmaf_rn(-0.7f, denom, inter);
            bool dec = d > 0.f;
            if (fabsf(d) < 1e-6f * denom) dec = (inter / denom) > 0.7f;
            if (dec) bits1 |= (1ull << c);
        }
    }
    if (i0 < PRE_K) g_mask[(size_t)i0 * NWP + cb] = bits0;
    if (do1 && i1 < PRE_K) g_mask[(size_t)i1 * NWP + cb] = bits1;
}

/* ---------------- K7: single-warp greedy NMS scan + output (fused) ------- */
__global__ void nms_out_kernel(float* __restrict__ out) {
    const unsigned FULL = 0xffffffffu;
    __shared__ u64 s_keep[NW];
    __shared__ u32 s_pref[NW];
    int lane = threadIdx.x;

    /* zero output (1500 floats = 375 float4) */
    float4* o4 = (float4*)out;
    for (int i = lane; i < 375; i += 32) o4[i] = make_float4(0.f, 0.f, 0.f, 0.f);
    __syncwarp();

    int w0 = 3 * lane;
    bool h1 = (w0 + 1) < NW, h2 = (w0 + 2) < NW;
    u64 rm0 = 0, rm1 = 0, rm2 = 0;
    u64 km0 = 0, km1 = 0, km2 = 0;
    u64 tv0 = g_tvalid[w0];
    u64 tv1 = h1 ? g_tvalid[w0 + 1] : 0ull;
    u64 tv2 = h2 ? g_tvalid[w0 + 2] : 0ull;
    int kept_total = 0;

    /* preload diagonal words for block 0 */
    int pr = 2 * lane;
    u64 m0 = g_mask[(size_t)pr * NWP + 0];
    u64 m1 = g_mask[(size_t)(pr + 1) * NWP + 0];

    for (int c = 0; c < NW; ++c) {
        /* prefetch next block's diagonal words */
        u64 n0 = 0ull, n1 = 0ull;
        if (c + 1 < NW) {
            int rr = (c + 1) * 64 + 2 * lane;
            if (rr     < PRE_K) n0 = g_mask[(size_t)rr       * NWP + (c + 1)];
            if (rr + 1 < PRE_K) n1 = g_mask[(size_t)(rr + 1) * NWP + (c + 1)];
        }

        int owner = c / 3;
        int slot  = c - 3 * owner;
        u64 myrem = (slot == 0) ? rm0 : ((slot == 1) ? rm1 : rm2);
        u64 mytv  = (slot == 0) ? tv0 : ((slot == 1) ? tv1 : tv2);
        u64 rem_c = __shfl_sync(FULL, myrem, owner);
        u64 tv_c  = __shfl_sync(FULL, mytv,  owner);

        u64 local = rem_c, keptmask = 0ull;
        u64 mb = tv_c & ~local;
        while (mb) {
            int k = __ffsll((long long)mb) - 1;
            u64 v = __shfl_sync(FULL, (k & 1) ? m1 : m0, k >> 1);
            keptmask |= (1ull << k);
            local |= v;
            mb = tv_c & ~local & ~((2ull << k) - 1ull);
        }

        if (lane == owner) {
            if (slot == 0) km0 = keptmask;
            else if (slot == 1) km1 = keptmask;
            else km2 = keptmask;
        }
        kept_total += __popcll(keptmask);
        if (kept_total >= POST_K) break;

        if (w0 + 2 > c) {
            u64 mbf = keptmask;
            while (mbf) {
                int rk[8];
                #pragma unroll
                for (int q = 0; q < 8; q++) {
                    if (mbf) { rk[q] = __ffsll((long long)mbf) - 1; mbf &= mbf - 1; }
                    else rk[q] = -1;
                }
                u64 o0 = 0ull, o1 = 0ull, o2 = 0ull;
                #pragma unroll
                for (int q = 0; q < 8; q++) {
                    if (rk[q] >= 0) {
                        const u64* p = &g_mask[(size_t)(c * 64 + rk[q]) * NWP + w0];
                        o0 |= p[0];
                        if (h1) o1 |= p[1];
                        if (h2) o2 |= p[2];
                    }
                }
                rm0 |= o0; rm1 |= o1; rm2 |= o2;
            }
        }
        m0 = n0; m1 = n1;
    }

    /* publish keep masks + prefix, then emit first 300 kept boxes */
    s_keep[w0] = km0;
    if (h1) s_keep[w0 + 1] = km1;
    if (h2) s_keep[w0 + 2] = km2;
    __syncwarp();
    if (lane == 0) {
        u32 run = 0;
        for (int w = 0; w < NW; ++w) { s_pref[w] = run; run += (u32)__popcll(s_keep[w]); }
    }
    __syncwarp();
    for (int i = lane; i < PRE_K; i += 32) {
        int w = i >> 6, b = i & 63;
        if (s_pref[w] >= POST_K) break;
        u64 kw = s_keep[w];
        if ((kw >> b) & 1ull) {
            u64 lowmask = (b == 0) ? 0ull : ((~0ull) >> (64 - b));
            u32 rank = s_pref[w] + (u32)__popcll(kw & lowmask);
            if (rank < POST_K) {
                float4 bx = g_nboxes[i];
                out[rank * 5 + 1] = bx.x;
                out[rank * 5 + 2] = bx.y;
                out[rank * 5 + 3] = bx.z;
                out[rank * 5 + 4] = bx.w;
            }
        }
    }
}

/* ---------------- launch ---------------- */
extern "C" void kernel_launch(void* const* d_in, const int* in_sizes, int n_in,
                              void* d_out, int out_size) {
    const float* scores = (const float*)d_in[0];
    const float* deltas = (const float*)d_in[1];
    const float* iminfo = (const float*)d_in[2];
    float* out = (float*)d_out;

    init_kernel<<<(INIT_ITEMS + 255) / 256, 256>>>();
    decode_kernel<<<NTOT / 256, 256>>>(scores, deltas, iminfo);
    thresh_kernel<<<1, 1024>>>();
    compact_kernel<<<(NTOT / 4) / 256, 256>>>();
    rank_count_kernel<<<dim3(SORT_CAP / 512, NSEG), 128>>>();
    scatter_gather_kernel<<<SORT_CAP / 256, 256>>>();
    iou_kernel<<<dim3(NW, (PRE_K + 127) / 128), 64>>>();
    nms_out_kernel<<<1, 32>>>(out);
}